// round 16
// baseline (speedup 1.0000x reference)
#include <cuda_runtime.h>
#include <cuda_fp16.h>
#include <cstdint>

#define NN 2048
#define DD 512
#define KPC 8
#define TM 128
#define TN 128
#define KS 64
#define NSLAB (DD / KS)
#define NGEMM 136          // 16*17/2 upper-triangular tiles

// ---------------- scratch (no allocations allowed) ----------------
__device__ __half g_xf[NN * DD];             // fp16 normalized (MMA operand)
__device__ float g_sq[NN];
__device__ float g_dist[(size_t)NN * NN];    // 16 MB distance matrix
__device__ float g_row[NN * 4];              // cnt, trip_sum, pos_sum, neg_sum
__device__ int g_done;

// ---------------- helpers ----------------
__device__ __forceinline__ uint32_t smem_to_u32(const void* p) {
    uint32_t a;
    asm("{ .reg .u64 t; cvta.to.shared.u64 t, %1; cvt.u32.u64 %0, t; }" : "=r"(a) : "l"(p));
    return a;
}
__device__ __forceinline__ float fast_exp2(float x) { float y; asm("ex2.approx.f32 %0, %1;" : "=f"(y) : "f"(x)); return y; }
__device__ __forceinline__ float fast_log2(float x) { float y; asm("lg2.approx.f32 %0, %1;" : "=f"(y) : "f"(x)); return y; }
__device__ __forceinline__ float warp_sum(float v) {
    #pragma unroll
    for (int o = 16; o; o >>= 1) v += __shfl_xor_sync(0xffffffffu, v, o);
    return v;
}

#define CPA(dst, src) \
    asm volatile("cp.async.cg.shared.global [%0], [%1], 16;" :: "r"(dst), "l"(src))
#define CPA_COMMIT() asm volatile("cp.async.commit_group;" ::: "memory")

__device__ __forceinline__ void ldm_x4(uint32_t* r, uint32_t addr) {
    asm volatile("ldmatrix.sync.aligned.m8n8.x4.shared.b16 {%0,%1,%2,%3}, [%4];"
                 : "=r"(r[0]), "=r"(r[1]), "=r"(r[2]), "=r"(r[3]) : "r"(addr));
}
__device__ __forceinline__ void mma_fp16(float* c, const uint32_t* a, uint32_t b0, uint32_t b1) {
    asm volatile(
        "mma.sync.aligned.m16n8k16.row.col.f32.f16.f16.f32 "
        "{%0,%1,%2,%3}, {%4,%5,%6,%7}, {%8,%9}, {%0,%1,%2,%3};"
        : "+f"(c[0]), "+f"(c[1]), "+f"(c[2]), "+f"(c[3])
        : "r"(a[0]), "r"(a[1]), "r"(a[2]), "r"(a[3]), "r"(b0), "r"(b1));
}

// ---------------------------------------------------------------------------
// 1) prep v2: 2 rows per CTA (128 threads/row), 1024 CTAs for latency hiding
// ---------------------------------------------------------------------------
__global__ __launch_bounds__(256) void prep_kernel(const float* __restrict__ in) {
    const int tid = threadIdx.x;
    const int sub = tid >> 7;            // row within block (0/1)
    const int t = tid & 127;             // thread within row
    const int row = blockIdx.x * 2 + sub;
    if (blockIdx.x == 0 && tid == 0) g_done = 0;

    float4 v = reinterpret_cast<const float4*>(in + row * DD)[t];
    float ss = v.x * v.x + v.y * v.y + v.z * v.z + v.w * v.w;
    ss = warp_sum(ss);
    __shared__ float ws[2][4];
    const int w4 = (tid >> 5) & 3;
    if ((tid & 31) == 0) ws[sub][w4] = ss;
    __syncthreads();
    const float tot = ws[sub][0] + ws[sub][1] + ws[sub][2] + ws[sub][3];
    const float s = 4.0f * rsqrtf(tot);

    __half2* pf = reinterpret_cast<__half2*>(g_xf + row * DD + t * 4);
    pf[0] = __half2(__float2half_rn(v.x * s), __float2half_rn(v.y * s));
    pf[1] = __half2(__float2half_rn(v.z * s), __float2half_rn(v.w * s));
    if (t == 0) g_sq[row] = tot * s * s;
}

// ---------------------------------------------------------------------------
// 2) gemm_kernel: symmetric HMMA Gram, 136 upper-tri 128x128 tiles (R13 winner)
// ---------------------------------------------------------------------------
#define SM_SQI 0
#define SM_SQJ 512
#define SM_BUF 1024
#define A_OFF 0
#define B_OFF 16384
#define BUFSZ 32768
#define TSTRIDE 132
#define SMEM_TOTAL (SM_BUF + TM * TSTRIDE * 4)   // 68608 > mainloop's 66560

__device__ __forceinline__ void load_slab_async(uint32_t smb, int buf, int s,
                                                int bi, int bj, int tid) {
    const int k0 = s * KS;
    const uint32_t bufb = smb + SM_BUF + buf * BUFSZ;
    const int row = tid >> 1;
    const int cb = (tid & 1) * 4;
    {
        const char* sp = reinterpret_cast<const char*>(g_xf + (bi + row) * DD + k0);
        uint32_t dA = bufb + A_OFF + row * 128;
        #pragma unroll
        for (int c = 0; c < 4; c++) {
            int ch = cb + c;
            CPA(dA + (((ch ^ (row & 7))) << 4), sp + ch * 16);
        }
    }
    {
        const char* sp = reinterpret_cast<const char*>(g_xf + (bj + row) * DD + k0);
        uint32_t dB = bufb + B_OFF + row * 128;
        #pragma unroll
        for (int c = 0; c < 4; c++) {
            int ch = cb + c;
            CPA(dB + (((ch ^ (row & 7))) << 4), sp + ch * 16);
        }
    }
}

__global__ __launch_bounds__(256, 2) void gemm_kernel() {
    extern __shared__ char smem[];
    const int tid = threadIdx.x;
    const int wid = tid >> 5;
    const int lane = tid & 31;

    int ti = 0, r = blockIdx.x, c = 16;
    while (r >= c) { r -= c; c--; ti++; }
    const int tj = ti + r;
    const int bi = ti * TM;
    const int bj = tj * TN;

    const int mloc = (wid >> 2) * 64;
    const int nloc = (wid & 3) * 32;
    const uint32_t smb = smem_to_u32(smem);
    float* sSqi = reinterpret_cast<float*>(smem + SM_SQI);
    float* sSqj = reinterpret_cast<float*>(smem + SM_SQJ);

    load_slab_async(smb, 0, 0, bi, bj, tid);
    CPA_COMMIT();

    if (tid < 128) sSqi[tid] = g_sq[bi + tid];
    else           sSqj[tid - 128] = g_sq[bj + (tid - 128)];

    float acc[4][4][4];
    #pragma unroll
    for (int mi = 0; mi < 4; mi++)
        #pragma unroll
        for (int ni = 0; ni < 4; ni++)
            #pragma unroll
            for (int rr = 0; rr < 4; rr++) acc[mi][ni][rr] = 0.0f;

    const int rA = (lane & 7) + (((lane >> 3) & 1) << 3);
    const int cSel = lane >> 4;
    const int x7 = lane & 7;
    uint32_t koff[4];
    #pragma unroll
    for (int ks = 0; ks < 4; ks++) koff[ks] = ((uint32_t)((2 * ks + cSel) ^ x7)) << 4;
    const uint32_t arow = (uint32_t)(mloc + rA) * 128;
    const uint32_t brow = (uint32_t)(nloc + rA) * 128;

    #pragma unroll 1
    for (int s = 0; s < NSLAB; s++) {
        const int b = s & 1;
        if (s + 1 < NSLAB) { load_slab_async(smb, 1 - b, s + 1, bi, bj, tid); CPA_COMMIT(); }
        if (s + 1 < NSLAB) asm volatile("cp.async.wait_group 1;" ::: "memory");
        else               asm volatile("cp.async.wait_group 0;" ::: "memory");
        __syncthreads();

        const uint32_t base = smb + SM_BUF + b * BUFSZ;
        const uint32_t baseA = base + A_OFF + arow;
        const uint32_t baseB = base + B_OFF + brow;
        #pragma unroll
        for (int ks = 0; ks < 4; ks++) {
            uint32_t af[4][4];
            #pragma unroll
            for (int mi = 0; mi < 4; mi++) ldm_x4(af[mi], baseA + mi * (16 * 128) + koff[ks]);
            uint32_t bfr[2][4];
            #pragma unroll
            for (int nt = 0; nt < 2; nt++) ldm_x4(bfr[nt], baseB + nt * (16 * 128) + koff[ks]);
            #pragma unroll
            for (int mi = 0; mi < 4; mi++)
                #pragma unroll
                for (int nt = 0; nt < 2; nt++) {
                    mma_fp16(acc[mi][2 * nt],     af[mi], bfr[nt][0], bfr[nt][2]);
                    mma_fp16(acc[mi][2 * nt + 1], af[mi], bfr[nt][1], bfr[nt][3]);
                }
        }
        __syncthreads();
    }

    #pragma unroll
    for (int mi = 0; mi < 4; mi++) {
        #pragma unroll
        for (int h = 0; h < 2; h++) {
            const int rl = mloc + mi * 16 + h * 8 + (lane >> 2);
            const float sqi = sSqi[rl];
            float* drow = g_dist + (size_t)(bi + rl) * NN + bj;
            #pragma unroll
            for (int ni = 0; ni < 4; ni++) {
                const int cl = nloc + ni * 8 + (lane & 3) * 2;
                float2 o;
                o.x = fmaf(-2.0f, acc[mi][ni][h * 2 + 0], sqi + sSqj[cl]);
                o.y = fmaf(-2.0f, acc[mi][ni][h * 2 + 1], sqi + sSqj[cl + 1]);
                *reinterpret_cast<float2*>(drow + cl) = o;
            }
        }
    }

    if (ti != tj) {
        float* sT = reinterpret_cast<float*>(smem + SM_BUF);  // 128 x 132
        #pragma unroll
        for (int mi = 0; mi < 4; mi++) {
            #pragma unroll
            for (int h = 0; h < 2; h++) {
                const int rl = mloc + mi * 16 + h * 8 + (lane >> 2);
                const float sqi = sSqi[rl];
                #pragma unroll
                for (int ni = 0; ni < 4; ni++) {
                    const int cl = nloc + ni * 8 + (lane & 3) * 2;
                    sT[(cl + 0) * TSTRIDE + rl] = fmaf(-2.0f, acc[mi][ni][h * 2 + 0], sqi + sSqj[cl]);
                    sT[(cl + 1) * TSTRIDE + rl] = fmaf(-2.0f, acc[mi][ni][h * 2 + 1], sqi + sSqj[cl + 1]);
                }
            }
        }
        __syncthreads();
        const int cc = tid >> 1, hf = tid & 1;
        float* dout = g_dist + (size_t)(bj + cc) * NN + bi + hf * 64;
        const float* srow = sT + cc * TSTRIDE + hf * 64;
        #pragma unroll
        for (int i = 0; i < 16; i++)
            reinterpret_cast<float4*>(dout)[i] = reinterpret_cast<const float4*>(srow)[i];
    }
}

// ---------------------------------------------------------------------------
// 3) triplet_kernel v2: one WARP per row, barrier-free hot path
// ---------------------------------------------------------------------------
__global__ __launch_bounds__(256) void triplet_kernel(float* __restrict__ out, int out_size) {
    const int tid = threadIdx.x;
    const int w = tid >> 5;
    const int l = tid & 31;
    const int row = blockIdx.x * 8 + w;
    const int cls = row >> 3;
    const float L2E = 1.4426950408889634f;
    const float LN2 = 0.6931471805599453f;

    const float* drow = g_dist + (size_t)row * NN;
    const float4* drow4 = reinterpret_cast<const float4*>(drow);

    // positives preamble: lane (l&7) loads one positive, broadcast via shfl
    const int kslot = l & 7;
    const float p = drow[cls * KPC + kslot];
    const bool self = (cls * KPC + kslot) == row;
    const float Pl = self ? 0.0f : fast_exp2(p * L2E);
    const float Tl = self ? -1.0e30f : (p + 2.9447e-4f);
    float P[8], T[8];
    #pragma unroll
    for (int k = 0; k < 8; k++) {
        P[k] = __shfl_sync(0xffffffffu, Pl, k);
        T[k] = __shfl_sync(0xffffffffu, Tl, k);
    }
    {
        float ps = (l < 8 && !self) ? p : 0.0f;
        ps = warp_sum(ps);
        if (l == 0) g_row[row * 4 + 2] = ps;
    }

    int ic = 0;
    float tr = 0.0f, ng = 0.0f;

    // 512 float4 per row / 32 lanes = 16 chunks; process in groups of 4 (MLP 4)
    #pragma unroll
    for (int g = 0; g < 4; g++) {
        float4 v[4];
        #pragma unroll
        for (int c = 0; c < 4; c++) v[c] = drow4[(g * 4 + c) * 32 + l];
        #pragma unroll
        for (int c = 0; c < 4; c++) {
            const int jbase = ((g * 4 + c) * 32 + l) * 4;
            if ((jbase >> 3) == cls) continue;   // whole float4 inside class block
            const float dd[4] = { v[c].x, v[c].y, v[c].z, v[c].w };
            #pragma unroll
            for (int q = 0; q < 4; q++) {
                const float d = dd[q];
                ng += d;
                const float en = fast_exp2(-d * L2E);
                const bool v0 = d < T[0], v1 = d < T[1], v2 = d < T[2], v3 = d < T[3];
                const bool v4 = d < T[4], v5 = d < T[5], v6 = d < T[6], v7 = d < T[7];
                ic += (int)v0 + (int)v1 + (int)v2 + (int)v3
                    + (int)v4 + (int)v5 + (int)v6 + (int)v7;
                float a0 = (v0 ? fmaf(P[0], en, 1.0f) : 1.0f) * (v1 ? fmaf(P[1], en, 1.0f) : 1.0f);
                float a1 = (v2 ? fmaf(P[2], en, 1.0f) : 1.0f) * (v3 ? fmaf(P[3], en, 1.0f) : 1.0f);
                float b0 = (v4 ? fmaf(P[4], en, 1.0f) : 1.0f) * (v5 ? fmaf(P[5], en, 1.0f) : 1.0f);
                float b1 = (v6 ? fmaf(P[6], en, 1.0f) : 1.0f) * (v7 ? fmaf(P[7], en, 1.0f) : 1.0f);
                tr += fast_log2(a0 * a1) + fast_log2(b0 * b1);
            }
        }
    }

    const float cs = warp_sum((float)ic);
    const float ts = warp_sum(LN2 * tr);
    const float ns = warp_sum(ng);
    if (l == 0) {
        g_row[row * 4 + 0] = cs;
        g_row[row * 4 + 1] = ts;
        g_row[row * 4 + 3] = ns;
    }

    // ---- last-block finalize ----
    __syncthreads();
    __shared__ int slast;
    if (tid == 0) {
        __threadfence();
        int o = atomicAdd(&g_done, 1);
        slast = (o == NN / 8 - 1);
    }
    __syncthreads();
    if (!slast) return;
    __threadfence();

    double sm = 0, tc = 0, acd = 0, psd = 0, nsd = 0;
    for (int i = tid; i < NN; i += 256) {
        float4 rr = *reinterpret_cast<const float4*>(g_row + i * 4);
        tc += (double)rr.x; psd += (double)rr.z; nsd += (double)rr.w;
        if (rr.x > 0.0f) sm += (double)(rr.y / rr.x);
        else             acd += 1.0;
    }
    #pragma unroll
    for (int o = 16; o; o >>= 1) {
        sm  += __shfl_xor_sync(0xffffffffu, sm, o);
        tc  += __shfl_xor_sync(0xffffffffu, tc, o);
        acd += __shfl_xor_sync(0xffffffffu, acd, o);
        psd += __shfl_xor_sync(0xffffffffu, psd, o);
        nsd += __shfl_xor_sync(0xffffffffu, nsd, o);
    }
    __shared__ double sh[5][8];
    if (l == 0) { sh[0][w] = sm; sh[1][w] = tc; sh[2][w] = acd; sh[3][w] = psd; sh[4][w] = nsd; }
    __syncthreads();
    if (tid == 0) {
        double Sm = 0, Tc = 0, Ac = 0, Ps = 0, Ns = 0;
        #pragma unroll
        for (int ww = 0; ww < 8; ww++) {
            Sm += sh[0][ww]; Tc += sh[1][ww]; Ac += sh[2][ww]; Ps += sh[3][ww]; Ns += sh[4][ww];
        }
        float loss = (Tc > 0.0) ? (float)(Sm / Tc) : 0.0f;
        if (out_size >= 1) out[0] = loss;
        if (out_size >= 2) out[1] = (float)(Ac / (double)NN);
        if (out_size >= 3) out[2] = (float)(Ps / ((double)NN * (KPC - 1)));
        if (out_size >= 4) out[3] = (float)(Ns / ((double)NN * (NN - KPC)));
    }
    for (int idx = 4 + tid; idx < out_size; idx += 256) out[idx] = 0.0f;
}

// ---------------------------------------------------------------------------
extern "C" void kernel_launch(void* const* d_in, const int* in_sizes, int n_in,
                              void* d_out, int out_size) {
    const float* inputs = (const float*)d_in[0];
    (void)in_sizes; (void)n_in;
    float* out = (float*)d_out;

    cudaFuncSetAttribute(gemm_kernel, cudaFuncAttributeMaxDynamicSharedMemorySize, SMEM_TOTAL);
    cudaFuncSetAttribute(gemm_kernel, cudaFuncAttributePreferredSharedMemoryCarveout, 100);

    prep_kernel<<<NN / 2, 256>>>(inputs);
    gemm_kernel<<<NGEMM, 256, SMEM_TOTAL>>>();
    triplet_kernel<<<NN / 8, 256>>>(out, out_size);
}

// round 17
// speedup vs baseline: 1.4716x; 1.4716x over previous
#include <cuda_runtime.h>
#include <cuda_fp16.h>
#include <cstdint>

#define NN 2048
#define DD 512
#define KPC 8
#define TM 128
#define TN 128
#define KS 64
#define NSLAB (DD / KS)
#define NGEMM 136          // 16*17/2 upper-triangular tiles
#define TRPC 4             // rows per triplet CTA (half class)
#define NTRIP (NN / TRPC)  // 512

// ---------------- scratch (no allocations allowed) ----------------
__device__ __half g_xf[NN * DD];             // fp16 normalized (MMA operand)
__device__ float g_sq[NN];
__device__ float g_dist[(size_t)NN * NN];    // 16 MB distance matrix
__device__ float g_row[NN * 4];              // cnt, trip_sum, pos_sum, neg_sum
__device__ int g_done;

// ---------------- helpers ----------------
__device__ __forceinline__ uint32_t smem_to_u32(const void* p) {
    uint32_t a;
    asm("{ .reg .u64 t; cvta.to.shared.u64 t, %1; cvt.u32.u64 %0, t; }" : "=r"(a) : "l"(p));
    return a;
}
__device__ __forceinline__ float fast_exp2(float x) { float y; asm("ex2.approx.f32 %0, %1;" : "=f"(y) : "f"(x)); return y; }
__device__ __forceinline__ float fast_log2(float x) { float y; asm("lg2.approx.f32 %0, %1;" : "=f"(y) : "f"(x)); return y; }
__device__ __forceinline__ float warp_sum(float v) {
    #pragma unroll
    for (int o = 16; o; o >>= 1) v += __shfl_xor_sync(0xffffffffu, v, o);
    return v;
}

#define CPA(dst, src) \
    asm volatile("cp.async.cg.shared.global [%0], [%1], 16;" :: "r"(dst), "l"(src))
#define CPA_COMMIT() asm volatile("cp.async.commit_group;" ::: "memory")

__device__ __forceinline__ void ldm_x4(uint32_t* r, uint32_t addr) {
    asm volatile("ldmatrix.sync.aligned.m8n8.x4.shared.b16 {%0,%1,%2,%3}, [%4];"
                 : "=r"(r[0]), "=r"(r[1]), "=r"(r[2]), "=r"(r[3]) : "r"(addr));
}
__device__ __forceinline__ void mma_fp16(float* c, const uint32_t* a, uint32_t b0, uint32_t b1) {
    asm volatile(
        "mma.sync.aligned.m16n8k16.row.col.f32.f16.f16.f32 "
        "{%0,%1,%2,%3}, {%4,%5,%6,%7}, {%8,%9}, {%0,%1,%2,%3};"
        : "+f"(c[0]), "+f"(c[1]), "+f"(c[2]), "+f"(c[3])
        : "r"(a[0]), "r"(a[1]), "r"(a[2]), "r"(a[3]), "r"(b0), "r"(b1));
}

// ---------------------------------------------------------------------------
// 1) prep: normalize + fp16 + sq (R13/R15 proven version)
// ---------------------------------------------------------------------------
__global__ __launch_bounds__(256) void prep_kernel(const float* __restrict__ in) {
    const int tid = threadIdx.x;
    const int w = tid >> 5;
    const int l = tid & 31;
    const int row = blockIdx.x * 8 + w;
    if (blockIdx.x == 0 && tid == 0) g_done = 0;

    float4 v[4];
    const float4* src = reinterpret_cast<const float4*>(in + row * DD) + l * 4;
    #pragma unroll
    for (int q = 0; q < 4; q++) v[q] = src[q];
    float ss = 0.0f;
    #pragma unroll
    for (int q = 0; q < 4; q++)
        ss += v[q].x * v[q].x + v[q].y * v[q].y + v[q].z * v[q].z + v[q].w * v[q].w;
    ss = warp_sum(ss);
    float s = 4.0f * rsqrtf(ss);

    __half2* pf = reinterpret_cast<__half2*>(g_xf + row * DD + l * 16);
    #pragma unroll
    for (int q = 0; q < 4; q++) {
        pf[q * 2 + 0] = __half2(__float2half_rn(v[q].x * s), __float2half_rn(v[q].y * s));
        pf[q * 2 + 1] = __half2(__float2half_rn(v[q].z * s), __float2half_rn(v[q].w * s));
    }
    if (l == 0) g_sq[row] = ss * s * s;
}

// ---------------------------------------------------------------------------
// 2) gemm_kernel: symmetric HMMA Gram, 136 upper-tri 128x128 tiles (R13 winner)
// ---------------------------------------------------------------------------
#define SM_SQI 0
#define SM_SQJ 512
#define SM_BUF 1024
#define A_OFF 0
#define B_OFF 16384
#define BUFSZ 32768
#define TSTRIDE 132
#define SMEM_TOTAL (SM_BUF + TM * TSTRIDE * 4)

__device__ __forceinline__ void load_slab_async(uint32_t smb, int buf, int s,
                                                int bi, int bj, int tid) {
    const int k0 = s * KS;
    const uint32_t bufb = smb + SM_BUF + buf * BUFSZ;
    const int row = tid >> 1;
    const int cb = (tid & 1) * 4;
    {
        const char* sp = reinterpret_cast<const char*>(g_xf + (bi + row) * DD + k0);
        uint32_t dA = bufb + A_OFF + row * 128;
        #pragma unroll
        for (int c = 0; c < 4; c++) {
            int ch = cb + c;
            CPA(dA + (((ch ^ (row & 7))) << 4), sp + ch * 16);
        }
    }
    {
        const char* sp = reinterpret_cast<const char*>(g_xf + (bj + row) * DD + k0);
        uint32_t dB = bufb + B_OFF + row * 128;
        #pragma unroll
        for (int c = 0; c < 4; c++) {
            int ch = cb + c;
            CPA(dB + (((ch ^ (row & 7))) << 4), sp + ch * 16);
        }
    }
}

__global__ __launch_bounds__(256, 2) void gemm_kernel() {
    extern __shared__ char smem[];
    const int tid = threadIdx.x;
    const int wid = tid >> 5;
    const int lane = tid & 31;

    int ti = 0, r = blockIdx.x, c = 16;
    while (r >= c) { r -= c; c--; ti++; }
    const int tj = ti + r;
    const int bi = ti * TM;
    const int bj = tj * TN;

    const int mloc = (wid >> 2) * 64;
    const int nloc = (wid & 3) * 32;
    const uint32_t smb = smem_to_u32(smem);
    float* sSqi = reinterpret_cast<float*>(smem + SM_SQI);
    float* sSqj = reinterpret_cast<float*>(smem + SM_SQJ);

    load_slab_async(smb, 0, 0, bi, bj, tid);
    CPA_COMMIT();

    if (tid < 128) sSqi[tid] = g_sq[bi + tid];
    else           sSqj[tid - 128] = g_sq[bj + (tid - 128)];

    float acc[4][4][4];
    #pragma unroll
    for (int mi = 0; mi < 4; mi++)
        #pragma unroll
        for (int ni = 0; ni < 4; ni++)
            #pragma unroll
            for (int rr = 0; rr < 4; rr++) acc[mi][ni][rr] = 0.0f;

    const int rA = (lane & 7) + (((lane >> 3) & 1) << 3);
    const int cSel = lane >> 4;
    const int x7 = lane & 7;
    uint32_t koff[4];
    #pragma unroll
    for (int ks = 0; ks < 4; ks++) koff[ks] = ((uint32_t)((2 * ks + cSel) ^ x7)) << 4;
    const uint32_t arow = (uint32_t)(mloc + rA) * 128;
    const uint32_t brow = (uint32_t)(nloc + rA) * 128;

    #pragma unroll 1
    for (int s = 0; s < NSLAB; s++) {
        const int b = s & 1;
        if (s + 1 < NSLAB) { load_slab_async(smb, 1 - b, s + 1, bi, bj, tid); CPA_COMMIT(); }
        if (s + 1 < NSLAB) asm volatile("cp.async.wait_group 1;" ::: "memory");
        else               asm volatile("cp.async.wait_group 0;" ::: "memory");
        __syncthreads();

        const uint32_t base = smb + SM_BUF + b * BUFSZ;
        const uint32_t baseA = base + A_OFF + arow;
        const uint32_t baseB = base + B_OFF + brow;
        #pragma unroll
        for (int ks = 0; ks < 4; ks++) {
            uint32_t af[4][4];
            #pragma unroll
            for (int mi = 0; mi < 4; mi++) ldm_x4(af[mi], baseA + mi * (16 * 128) + koff[ks]);
            uint32_t bfr[2][4];
            #pragma unroll
            for (int nt = 0; nt < 2; nt++) ldm_x4(bfr[nt], baseB + nt * (16 * 128) + koff[ks]);
            #pragma unroll
            for (int mi = 0; mi < 4; mi++)
                #pragma unroll
                for (int nt = 0; nt < 2; nt++) {
                    mma_fp16(acc[mi][2 * nt],     af[mi], bfr[nt][0], bfr[nt][2]);
                    mma_fp16(acc[mi][2 * nt + 1], af[mi], bfr[nt][1], bfr[nt][3]);
                }
        }
        __syncthreads();
    }

    #pragma unroll
    for (int mi = 0; mi < 4; mi++) {
        #pragma unroll
        for (int h = 0; h < 2; h++) {
            const int rl = mloc + mi * 16 + h * 8 + (lane >> 2);
            const float sqi = sSqi[rl];
            float* drow = g_dist + (size_t)(bi + rl) * NN + bj;
            #pragma unroll
            for (int ni = 0; ni < 4; ni++) {
                const int cl = nloc + ni * 8 + (lane & 3) * 2;
                float2 o;
                o.x = fmaf(-2.0f, acc[mi][ni][h * 2 + 0], sqi + sSqj[cl]);
                o.y = fmaf(-2.0f, acc[mi][ni][h * 2 + 1], sqi + sSqj[cl + 1]);
                *reinterpret_cast<float2*>(drow + cl) = o;
            }
        }
    }

    if (ti != tj) {
        float* sT = reinterpret_cast<float*>(smem + SM_BUF);  // 128 x 132
        #pragma unroll
        for (int mi = 0; mi < 4; mi++) {
            #pragma unroll
            for (int h = 0; h < 2; h++) {
                const int rl = mloc + mi * 16 + h * 8 + (lane >> 2);
                const float sqi = sSqi[rl];
                #pragma unroll
                for (int ni = 0; ni < 4; ni++) {
                    const int cl = nloc + ni * 8 + (lane & 3) * 2;
                    sT[(cl + 0) * TSTRIDE + rl] = fmaf(-2.0f, acc[mi][ni][h * 2 + 0], sqi + sSqj[cl]);
                    sT[(cl + 1) * TSTRIDE + rl] = fmaf(-2.0f, acc[mi][ni][h * 2 + 1], sqi + sSqj[cl + 1]);
                }
            }
        }
        __syncthreads();
        const int cc = tid >> 1, hf = tid & 1;
        float* dout = g_dist + (size_t)(bj + cc) * NN + bi + hf * 64;
        const float* srow = sT + cc * TSTRIDE + hf * 64;
        #pragma unroll
        for (int i = 0; i < 16; i++)
            reinterpret_cast<float4*>(dout)[i] = reinterpret_cast<const float4*>(srow)[i];
    }
}

// ---------------------------------------------------------------------------
// 3) triplet_kernel v3: 4 rows (half class) per CTA, register double-buffer,
//    amortized positives + batched reductions; fused last-block finalize
// ---------------------------------------------------------------------------
__global__ __launch_bounds__(256) void triplet_kernel(float* __restrict__ out, int out_size) {
    const int row0 = blockIdx.x * TRPC;
    const int cls = row0 >> 3;
    const int tid = threadIdx.x;
    const int w = tid >> 5;
    const int l = tid & 31;
    const float L2E = 1.4426950408889634f;
    const float LN2 = 0.6931471805599453f;

    __shared__ float sP[TRPC][8], sT[TRPC][8];

    // preamble (warp 0): 4x8 positive sub-block, P/T + pos_sum per row
    if (w == 0) {
        const int r = l >> 3, k = l & 7;
        const int row = row0 + r;
        const float p = g_dist[(size_t)row * NN + cls * KPC + k];
        const bool self = (cls * KPC + k) == row;
        sP[r][k] = self ? 0.0f : fast_exp2(p * L2E);
        sT[r][k] = self ? -1.0e30f : (p + 2.9447e-4f);
        float ps = self ? 0.0f : p;
        ps += __shfl_xor_sync(0xffffffffu, ps, 1);
        ps += __shfl_xor_sync(0xffffffffu, ps, 2);
        ps += __shfl_xor_sync(0xffffffffu, ps, 4);
        if (k == 0) g_row[row * 4 + 2] = ps;
    }

    // kick off row0 loads before waiting on the preamble
    const float4* base4 = reinterpret_cast<const float4*>(g_dist + (size_t)row0 * NN);
    float4 curA = base4[tid];
    float4 curB = base4[256 + tid];
    __syncthreads();

    const bool skipA = ((tid >> 1) == cls);
    const bool skipB = ((128 + (tid >> 1)) == cls);

    float icr[TRPC], trr[TRPC], ngr[TRPC];
    #pragma unroll
    for (int r = 0; r < TRPC; r++) { icr[r] = 0.0f; trr[r] = 0.0f; ngr[r] = 0.0f; }

    #pragma unroll
    for (int r = 0; r < TRPC; r++) {
        // prefetch next row
        float4 nxtA, nxtB;
        if (r + 1 < TRPC) {
            const float4* nb = reinterpret_cast<const float4*>(g_dist + (size_t)(row0 + r + 1) * NN);
            nxtA = nb[tid];
            nxtB = nb[256 + tid];
        }
        float P[8], T[8];
        #pragma unroll
        for (int k = 0; k < 8; k++) { P[k] = sP[r][k]; T[k] = sT[r][k]; }

        int ic = 0;
        float tr = 0.0f, ng = 0.0f;
        #pragma unroll
        for (int hb = 0; hb < 2; hb++) {
            if (hb == 0 ? skipA : skipB) continue;
            const float4 v = hb ? curB : curA;
            const float dd[4] = { v.x, v.y, v.z, v.w };
            #pragma unroll
            for (int q = 0; q < 4; q++) {
                const float d = dd[q];
                ng += d;
                const float en = fast_exp2(-d * L2E);
                const bool v0 = d < T[0], v1 = d < T[1], v2 = d < T[2], v3 = d < T[3];
                const bool v4 = d < T[4], v5 = d < T[5], v6 = d < T[6], v7 = d < T[7];
                ic += (int)v0 + (int)v1 + (int)v2 + (int)v3
                    + (int)v4 + (int)v5 + (int)v6 + (int)v7;
                float a0 = (v0 ? fmaf(P[0], en, 1.0f) : 1.0f) * (v1 ? fmaf(P[1], en, 1.0f) : 1.0f);
                float a1 = (v2 ? fmaf(P[2], en, 1.0f) : 1.0f) * (v3 ? fmaf(P[3], en, 1.0f) : 1.0f);
                float b0 = (v4 ? fmaf(P[4], en, 1.0f) : 1.0f) * (v5 ? fmaf(P[5], en, 1.0f) : 1.0f);
                float b1 = (v6 ? fmaf(P[6], en, 1.0f) : 1.0f) * (v7 ? fmaf(P[7], en, 1.0f) : 1.0f);
                tr += fast_log2(a0 * a1) + fast_log2(b0 * b1);
            }
        }
        icr[r] = (float)ic;
        trr[r] = LN2 * tr;
        ngr[r] = ng;
        curA = nxtA;
        curB = nxtB;
    }

    // batched reductions: 12 warp sums, one smem pass
    __shared__ float red[12][8];
    #pragma unroll
    for (int r = 0; r < TRPC; r++) {
        const float cs = warp_sum(icr[r]);
        const float ts = warp_sum(trr[r]);
        const float ns = warp_sum(ngr[r]);
        if (l == 0) { red[r * 3 + 0][w] = cs; red[r * 3 + 1][w] = ts; red[r * 3 + 2][w] = ns; }
    }
    __syncthreads();
    if (tid < 12) {
        float v = 0.0f;
        #pragma unroll
        for (int ww = 0; ww < 8; ww++) v += red[tid][ww];
        const int r = tid / 3, m = tid % 3;
        const int row = row0 + r;
        g_row[row * 4 + (m == 0 ? 0 : (m == 1 ? 1 : 3))] = v;
    }

    // ---- last-block finalize ----
    __syncthreads();
    __shared__ int slast;
    if (tid == 0) {
        __threadfence();
        int o = atomicAdd(&g_done, 1);
        slast = (o == NTRIP - 1);
    }
    __syncthreads();
    if (!slast) return;
    __threadfence();

    double sm = 0, tc = 0, acd = 0, psd = 0, nsd = 0;
    for (int i = tid; i < NN; i += 256) {
        float4 rr = *reinterpret_cast<const float4*>(g_row + i * 4);
        tc += (double)rr.x; psd += (double)rr.z; nsd += (double)rr.w;
        if (rr.x > 0.0f) sm += (double)(rr.y / rr.x);
        else             acd += 1.0;
    }
    #pragma unroll
    for (int o = 16; o; o >>= 1) {
        sm  += __shfl_xor_sync(0xffffffffu, sm, o);
        tc  += __shfl_xor_sync(0xffffffffu, tc, o);
        acd += __shfl_xor_sync(0xffffffffu, acd, o);
        psd += __shfl_xor_sync(0xffffffffu, psd, o);
        nsd += __shfl_xor_sync(0xffffffffu, nsd, o);
    }
    __shared__ double sh[5][8];
    if (l == 0) { sh[0][w] = sm; sh[1][w] = tc; sh[2][w] = acd; sh[3][w] = psd; sh[4][w] = nsd; }
    __syncthreads();
    if (tid == 0) {
        double Sm = 0, Tc = 0, Ac = 0, Ps = 0, Ns = 0;
        #pragma unroll
        for (int ww = 0; ww < 8; ww++) {
            Sm += sh[0][ww]; Tc += sh[1][ww]; Ac += sh[2][ww]; Ps += sh[3][ww]; Ns += sh[4][ww];
        }
        float loss = (Tc > 0.0) ? (float)(Sm / Tc) : 0.0f;
        if (out_size >= 1) out[0] = loss;
        if (out_size >= 2) out[1] = (float)(Ac / (double)NN);
        if (out_size >= 3) out[2] = (float)(Ps / ((double)NN * (KPC - 1)));
        if (out_size >= 4) out[3] = (float)(Ns / ((double)NN * (NN - KPC)));
    }
    for (int idx = 4 + tid; idx < out_size; idx += 256) out[idx] = 0.0f;
}

// ---------------------------------------------------------------------------
extern "C" void kernel_launch(void* const* d_in, const int* in_sizes, int n_in,
                              void* d_out, int out_size) {
    const float* inputs = (const float*)d_in[0];
    (void)in_sizes; (void)n_in;
    float* out = (float*)d_out;

    cudaFuncSetAttribute(gemm_kernel, cudaFuncAttributeMaxDynamicSharedMemorySize, SMEM_TOTAL);
    cudaFuncSetAttribute(gemm_kernel, cudaFuncAttributePreferredSharedMemoryCarveout, 100);

    prep_kernel<<<NN / 8, 256>>>(inputs);
    gemm_kernel<<<NGEMM, 256, SMEM_TOTAL>>>();
    triplet_kernel<<<NTRIP, 256>>>(out, out_size);
}